// round 4
// baseline (speedup 1.0000x reference)
#include <cuda_runtime.h>
#include <math.h>

#define TB 32          // batch elements per CTA (lane == element)
#define NTHREADS 512   // 16 warps

// Shared memory layout (floats), total 37632 floats = 150528 B:
//   sig : [0, 21120)        640 x 32, row stride 33 (bank-conflict-free)
//   mag : [21120, 37632)    129 x 4 x 32
//   y1  : [0, 16384)        128 x 4 x 32   (overwrites dead sig)
//   y2  : [16384, 20480)    64 x 2 x 32    (dead sig region, after y1)
//   y3  : [21120, 23168)    64 x 32        (dead mag region)
//   y4  : [23168, 27264)    128 x 32       (dead mag region)
//   part: [27264, 27776)    16 x 32
#define SMEM_FLOATS 37632

static __device__ __forceinline__ float sigmoidf_(float x) {
    return 1.0f / (1.0f + __expf(-x));
}

__global__ void __launch_bounds__(NTHREADS, 1)
vad_fused(const float* __restrict__ data,
          const float* __restrict__ stft_w,
          const float* __restrict__ e1_w, const float* __restrict__ e1_b,
          const float* __restrict__ e2_w, const float* __restrict__ e2_b,
          const float* __restrict__ e3_w, const float* __restrict__ e3_b,
          const float* __restrict__ e4_w, const float* __restrict__ e4_b,
          const float* __restrict__ w_ih,
          const float* __restrict__ b_ih, const float* __restrict__ b_hh,
          const float* __restrict__ dec_w, const float* __restrict__ dec_b,
          float* __restrict__ out)
{
    extern __shared__ float sm[];
    const int tid  = threadIdx.x;
    const int wid  = tid >> 5;
    const int lane = tid & 31;
    const long long e0 = (long long)blockIdx.x * TB;
    const float* __restrict__ dbase = data + e0 * 512;

    float* sig = sm;            // 640 x 32, stride 33
    float* mag = sm + 21120;    // 129 x 4 x 32

    // ---------------- build padded signal (transposed) ----------------
    // s[0..63]=0 (context), s[64..575]=data[0..511], s[576+j]=data[510-j] (reflect)
    for (int idx = tid; idx < 64 * TB; idx += NTHREADS) {
        int p = idx >> 5, e = idx & 31;
        sig[p * 33 + e] = 0.0f;
    }
    for (int idx = tid; idx < 512 * TB; idx += NTHREADS) {
        int e = idx >> 9, j = idx & 511;
        sig[(64 + j) * 33 + e] = dbase[idx];          // coalesced read
    }
    for (int idx = tid; idx < 64 * TB; idx += NTHREADS) {
        int e = idx >> 6, j = idx & 63;
        sig[(576 + j) * 33 + e] = dbase[e * 512 + 510 - j];
    }
    __syncthreads();

    // ---------------- STFT + magnitude ----------------
    // frame t uses s[128t + k], k=0..255; filters f (real) and f+129 (imag)
    // warp handles 2 filter-pairs at a time; 65 sets over 16 warps
    for (int s = wid; s < 65; s += 16) {
        int fa = 2 * s;
        int fb = 2 * s + 1;
        int fbc = (fb <= 128) ? fb : fa;   // clamp (no OOB), skip store below
        const float4* wra = (const float4*)(stft_w + fa * 256);
        const float4* wia = (const float4*)(stft_w + (fa + 129) * 256);
        const float4* wrb = (const float4*)(stft_w + fbc * 256);
        const float4* wib = (const float4*)(stft_w + (fbc + 129) * 256);

        float ar0 = 0, ar1 = 0, ar2 = 0, ar3 = 0;
        float ai0 = 0, ai1 = 0, ai2 = 0, ai3 = 0;
        float br0 = 0, br1 = 0, br2 = 0, br3 = 0;
        float bi0 = 0, bi1 = 0, bi2 = 0, bi3 = 0;
        const float* sp = sig + lane;

        #pragma unroll 2
        for (int k4 = 0; k4 < 64; ++k4) {
            float4 war = wra[k4];
            float4 wai = wia[k4];
            float4 wbr = wrb[k4];
            float4 wbi = wib[k4];
            #pragma unroll
            for (int u = 0; u < 4; ++u) {
                int k = k4 * 4 + u;
                float s0 = sp[k * 33];
                float s1 = sp[(128 + k) * 33];
                float s2 = sp[(256 + k) * 33];
                float s3 = sp[(384 + k) * 33];
                float wr = (&war.x)[u], wi = (&wai.x)[u];
                float vr = (&wbr.x)[u], vi = (&wbi.x)[u];
                ar0 = fmaf(wr, s0, ar0); ar1 = fmaf(wr, s1, ar1);
                ar2 = fmaf(wr, s2, ar2); ar3 = fmaf(wr, s3, ar3);
                ai0 = fmaf(wi, s0, ai0); ai1 = fmaf(wi, s1, ai1);
                ai2 = fmaf(wi, s2, ai2); ai3 = fmaf(wi, s3, ai3);
                br0 = fmaf(vr, s0, br0); br1 = fmaf(vr, s1, br1);
                br2 = fmaf(vr, s2, br2); br3 = fmaf(vr, s3, br3);
                bi0 = fmaf(vi, s0, bi0); bi1 = fmaf(vi, s1, bi1);
                bi2 = fmaf(vi, s2, bi2); bi3 = fmaf(vi, s3, bi3);
            }
        }
        float* ma = mag + fa * 128 + lane;
        ma[0]  = sqrtf(ar0 * ar0 + ai0 * ai0);
        ma[32] = sqrtf(ar1 * ar1 + ai1 * ai1);
        ma[64] = sqrtf(ar2 * ar2 + ai2 * ai2);
        ma[96] = sqrtf(ar3 * ar3 + ai3 * ai3);
        if (fb <= 128) {
            float* mb = mag + fb * 128 + lane;
            mb[0]  = sqrtf(br0 * br0 + bi0 * bi0);
            mb[32] = sqrtf(br1 * br1 + bi1 * bi1);
            mb[64] = sqrtf(br2 * br2 + bi2 * bi2);
            mb[96] = sqrtf(br3 * br3 + bi3 * bi3);
        }
    }
    __syncthreads();

    // ---------------- e1: conv(129->128, k3, s1, p1), len 4 -> 4, relu ----------------
    float* y1 = sm;   // 128 x 4 x 32 (sig region is dead)
    for (int s = wid; s < 64; s += 16) {
        int oa = 2 * s, ob = 2 * s + 1;
        const float* wA = e1_w + oa * 387;
        const float* wB = e1_w + ob * 387;
        float ba = e1_b[oa], bb = e1_b[ob];
        float a0 = ba, a1 = ba, a2 = ba, a3 = ba;
        float q0 = bb, q1 = bb, q2 = bb, q3 = bb;
        const float* mp = mag + lane;
        #pragma unroll 2
        for (int c = 0; c < 129; ++c) {
            float m0 = mp[c * 128];
            float m1 = mp[c * 128 + 32];
            float m2 = mp[c * 128 + 64];
            float m3 = mp[c * 128 + 96];
            float wa0 = wA[3 * c], wa1 = wA[3 * c + 1], wa2 = wA[3 * c + 2];
            float wb0 = wB[3 * c], wb1 = wB[3 * c + 1], wb2 = wB[3 * c + 2];
            a0 = fmaf(wa1, m0, fmaf(wa2, m1, a0));
            a1 = fmaf(wa0, m0, fmaf(wa1, m1, fmaf(wa2, m2, a1)));
            a2 = fmaf(wa0, m1, fmaf(wa1, m2, fmaf(wa2, m3, a2)));
            a3 = fmaf(wa0, m2, fmaf(wa1, m3, a3));
            q0 = fmaf(wb1, m0, fmaf(wb2, m1, q0));
            q1 = fmaf(wb0, m0, fmaf(wb1, m1, fmaf(wb2, m2, q1)));
            q2 = fmaf(wb0, m1, fmaf(wb1, m2, fmaf(wb2, m3, q2)));
            q3 = fmaf(wb0, m2, fmaf(wb1, m3, q3));
        }
        float* ya = y1 + oa * 128 + lane;
        ya[0] = fmaxf(a0, 0.f); ya[32] = fmaxf(a1, 0.f);
        ya[64] = fmaxf(a2, 0.f); ya[96] = fmaxf(a3, 0.f);
        float* yb = y1 + ob * 128 + lane;
        yb[0] = fmaxf(q0, 0.f); yb[32] = fmaxf(q1, 0.f);
        yb[64] = fmaxf(q2, 0.f); yb[96] = fmaxf(q3, 0.f);
    }
    __syncthreads();

    // ---------------- e2: conv(128->64, k3, s2, p1), len 4 -> 2, relu ----------------
    float* y2 = sm + 16384;  // 64 x 2 x 32
    {
        int obase = wid * 4;           // 16 warps x 4 = 64 channels
        float acc0[4], acc1[4];
        #pragma unroll
        for (int i = 0; i < 4; ++i) {
            float b = e2_b[obase + i];
            acc0[i] = b; acc1[i] = b;
        }
        const float* yp = y1 + lane;
        #pragma unroll 2
        for (int c = 0; c < 128; ++c) {
            float v0 = yp[c * 128];
            float v1 = yp[c * 128 + 32];
            float v2 = yp[c * 128 + 64];
            float v3 = yp[c * 128 + 96];
            #pragma unroll
            for (int i = 0; i < 4; ++i) {
                const float* w = e2_w + (obase + i) * 384 + 3 * c;
                float w0 = w[0], w1 = w[1], w2 = w[2];
                acc0[i] = fmaf(w1, v0, fmaf(w2, v1, acc0[i]));                 // t'=0: idx {-1,0,1}
                acc1[i] = fmaf(w0, v1, fmaf(w1, v2, fmaf(w2, v3, acc1[i])));   // t'=1: idx {1,2,3}
            }
        }
        #pragma unroll
        for (int i = 0; i < 4; ++i) {
            y2[(obase + i) * 64 + lane]      = fmaxf(acc0[i], 0.f);
            y2[(obase + i) * 64 + 32 + lane] = fmaxf(acc1[i], 0.f);
        }
    }
    __syncthreads();

    // ---------------- e3: conv(64->64, k3, s2, p1), len 2 -> 1, relu ----------------
    float* y3 = sm + 21120;  // 64 x 32 (mag region dead)
    {
        int obase = wid * 4;
        float acc[4];
        #pragma unroll
        for (int i = 0; i < 4; ++i) acc[i] = e3_b[obase + i];
        const float* yp = y2 + lane;
        #pragma unroll 2
        for (int c = 0; c < 64; ++c) {
            float v0 = yp[c * 64];
            float v1 = yp[c * 64 + 32];
            #pragma unroll
            for (int i = 0; i < 4; ++i) {
                const float* w = e3_w + (obase + i) * 192 + 3 * c;
                acc[i] = fmaf(w[1], v0, fmaf(w[2], v1, acc[i]));   // idx {-1,0,1} -> {0,1}
            }
        }
        #pragma unroll
        for (int i = 0; i < 4; ++i)
            y3[(obase + i) * 32 + lane] = fmaxf(acc[i], 0.f);
    }
    __syncthreads();

    // ---------------- e4: conv(64->128, k3, s1, p1), len 1 -> 1 (only center tap), relu ----------------
    float* y4 = sm + 23168;  // 128 x 32
    {
        int obase = wid * 8;
        float acc[8];
        #pragma unroll
        for (int i = 0; i < 8; ++i) acc[i] = e4_b[obase + i];
        const float* yp = y3 + lane;
        #pragma unroll 2
        for (int c = 0; c < 64; ++c) {
            float v = yp[c * 32];
            #pragma unroll
            for (int i = 0; i < 8; ++i)
                acc[i] = fmaf(e4_w[(obase + i) * 192 + 3 * c + 1], v, acc[i]);
        }
        #pragma unroll
        for (int i = 0; i < 8; ++i)
            y4[(obase + i) * 32 + lane] = fmaxf(acc[i], 0.f);
    }
    __syncthreads();

    // ---------------- LSTM cell (h0=c0=0 => only i,g,o gates) + decoder dot ----------------
    float* part = sm + 27264;  // 16 x 32
    {
        float psum = 0.f;
        #pragma unroll
        for (int i = 0; i < 8; ++i) {
            int ch = wid * 8 + i;
            float gi = b_ih[ch]       + b_hh[ch];
            float gg = b_ih[ch + 256] + b_hh[ch + 256];
            float go = b_ih[ch + 384] + b_hh[ch + 384];
            const float4* wi4 = (const float4*)(w_ih + ch * 128);
            const float4* wg4 = (const float4*)(w_ih + (ch + 256) * 128);
            const float4* wo4 = (const float4*)(w_ih + (ch + 384) * 128);
            const float* yp = y4 + lane;
            #pragma unroll 4
            for (int c4 = 0; c4 < 32; ++c4) {
                float4 wi = wi4[c4], wg = wg4[c4], wo = wo4[c4];
                #pragma unroll
                for (int u = 0; u < 4; ++u) {
                    float v = yp[(c4 * 4 + u) * 32];
                    gi = fmaf((&wi.x)[u], v, gi);
                    gg = fmaf((&wg.x)[u], v, gg);
                    go = fmaf((&wo.x)[u], v, go);
                }
            }
            float cnew = sigmoidf_(gi) * tanhf(gg);
            float h    = sigmoidf_(go) * tanhf(cnew);
            psum = fmaf(fmaxf(h, 0.f), dec_w[ch], psum);
        }
        part[wid * 32 + lane] = psum;
    }
    __syncthreads();

    if (wid == 0) {
        float acc = dec_b[0];
        #pragma unroll
        for (int w = 0; w < 16; ++w) acc += part[w * 32 + lane];
        out[e0 + lane] = sigmoidf_(acc);
    }
}

extern "C" void kernel_launch(void* const* d_in, const int* in_sizes, int n_in,
                              void* d_out, int out_size)
{
    const float* data   = (const float*)d_in[0];
    // d_in[1] = sr (always 16000 in this dataset -> context 64; unused)
    const float* stft_w = (const float*)d_in[2];
    const float* e1_w   = (const float*)d_in[3];
    const float* e1_b   = (const float*)d_in[4];
    const float* e2_w   = (const float*)d_in[5];
    const float* e2_b   = (const float*)d_in[6];
    const float* e3_w   = (const float*)d_in[7];
    const float* e3_b   = (const float*)d_in[8];
    const float* e4_w   = (const float*)d_in[9];
    const float* e4_b   = (const float*)d_in[10];
    const float* w_ih   = (const float*)d_in[11];
    // d_in[12] = w_hh (unused: h0 = 0)
    const float* b_ih   = (const float*)d_in[13];
    const float* b_hh   = (const float*)d_in[14];
    const float* dec_w  = (const float*)d_in[15];
    const float* dec_b  = (const float*)d_in[16];
    float* out = (float*)d_out;

    int B = in_sizes[0] / 512;
    int grid = B / TB;
    size_t smem = SMEM_FLOATS * sizeof(float);
    cudaFuncSetAttribute(vad_fused, cudaFuncAttributeMaxDynamicSharedMemorySize, (int)smem);
    vad_fused<<<grid, NTHREADS, smem>>>(data, stft_w,
                                        e1_w, e1_b, e2_w, e2_b, e3_w, e3_b, e4_w, e4_b,
                                        w_ih, b_ih, b_hh, dec_w, dec_b, out);
}

// round 6
// speedup vs baseline: 1.4267x; 1.4267x over previous
#include <cuda_runtime.h>
#include <math.h>

#define TB 32          // batch elements per CTA (lane == element)
#define NTHREADS 512   // 16 warps

// ---------------- shared memory layout (float offsets) ----------------
// phase A: SIGT  [32768, 53888)   640 x 32, stride 33 (transposed padded signal)
// phase B: SIG2  [0, 32768)       [k=256][e=32][t=4]  (frame-quad layout)
// phase C: MAG   [32768, 49280)   [c=129][e][t=4]     (overwrites dead SIGT)
//          FPART [49280, 53376)   16 warps x 32 e x (4t x re/im)
// phase D: Y1    [0, 16384)       [c=128][e][4]       (overwrites dead SIG2)
//          Y2    [16384, 20480)   [c=64][e][2]
//          Y3    [20480, 22528)   [c=64][e]
//          Y4    [22528, 26624)   [q=32][e][4]  (channel quads)
//          PART  [26624, 27136)
#define SIG2  0
#define SIGT  32768
#define MAG   32768
#define FPART 49280
#define Y1    0
#define Y2    16384
#define Y3    20480
#define Y4    22528
#define PARTS 26624
#define SMEM_FLOATS 53888

// ---------------- packed-weight scratch (__device__ globals, filled by prep) ----
__device__ float g_stft_wp[256 * 264];      // [k][2f interleaved (re,im)], row padded to 264
__device__ float g_e1_wp[32 * 129 * 12];    // [g(4ch)][c][j*4 + ch_in_quad]
__device__ float g_e2_wp[16 * 128 * 12];    // [g][c][j*4 + m]
__device__ float g_e3_wp[16 * 64 * 8];      // [g][c][ch0:(w1,w2), ch1:(w1,w2), ...]
__device__ float g_e4_wp[32 * 64 * 4];      // [g][c][center tap for 4 ch]

typedef unsigned long long f32x2;

static __device__ __forceinline__ f32x2 b2(float v) {
    f32x2 r; unsigned u = __float_as_uint(v);
    asm("mov.b64 %0, {%1,%2};" : "=l"(r) : "r"(u), "r"(u));
    return r;
}
static __device__ __forceinline__ void up2(f32x2 v, float& lo, float& hi) {
    unsigned a, b;
    asm("mov.b64 {%0,%1}, %2;" : "=r"(a), "=r"(b) : "l"(v));
    lo = __uint_as_float(a); hi = __uint_as_float(b);
}
static __device__ __forceinline__ f32x2 ffma2(f32x2 a, f32x2 b, f32x2 c) {
    f32x2 d;
    asm("fma.rn.f32x2 %0, %1, %2, %3;" : "=l"(d) : "l"(a), "l"(b), "l"(c));
    return d;
}
static __device__ __forceinline__ float sigmoidf_(float x) {
    return 1.0f / (1.0f + __expf(-x));
}

// ---------------- weight prep (runs each launch; ~5us) ----------------
__global__ void vad_prep(const float* __restrict__ stft_w,
                         const float* __restrict__ e1_w,
                         const float* __restrict__ e2_w,
                         const float* __restrict__ e3_w,
                         const float* __restrict__ e4_w)
{
    int t0 = blockIdx.x * blockDim.x + threadIdx.x;
    int stride = gridDim.x * blockDim.x;
    for (int i = t0; i < 256 * 129; i += stride) {
        int k = i / 129, f = i - k * 129;
        g_stft_wp[k * 264 + 2 * f]     = stft_w[f * 256 + k];
        g_stft_wp[k * 264 + 2 * f + 1] = stft_w[(f + 129) * 256 + k];
    }
    for (int i = t0; i < 32 * 129 * 12; i += stride) {
        int g = i / (129 * 12), r = i - g * 129 * 12, c = r / 12, jm = r - c * 12;
        int j = jm >> 2, m = jm & 3;
        g_e1_wp[i] = e1_w[(4 * g + m) * 387 + c * 3 + j];
    }
    for (int i = t0; i < 16 * 128 * 12; i += stride) {
        int g = i / (128 * 12), r = i - g * 128 * 12, c = r / 12, jm = r - c * 12;
        int j = jm >> 2, m = jm & 3;
        g_e2_wp[i] = e2_w[(4 * g + m) * 384 + c * 3 + j];
    }
    for (int i = t0; i < 16 * 64 * 8; i += stride) {
        int g = i / (64 * 8), r = i - g * 64 * 8, c = r / 8, m2 = r - c * 8;
        int m = m2 >> 1, j = 1 + (m2 & 1);
        g_e3_wp[i] = e3_w[(4 * g + m) * 192 + c * 3 + j];
    }
    for (int i = t0; i < 32 * 64 * 4; i += stride) {
        int g = i / (64 * 4), r = i - g * 64 * 4, c = r / 4, m = r - c * 4;
        g_e4_wp[i] = e4_w[(4 * g + m) * 192 + c * 3 + 1];
    }
}

// ---------------- main fused kernel ----------------
__global__ void __launch_bounds__(NTHREADS, 1)
vad_fused(const float* __restrict__ data,
          const float* __restrict__ e1_b, const float* __restrict__ e2_b,
          const float* __restrict__ e3_b, const float* __restrict__ e4_b,
          const float* __restrict__ w_ih,
          const float* __restrict__ b_ih, const float* __restrict__ b_hh,
          const float* __restrict__ dec_w, const float* __restrict__ dec_b,
          float* __restrict__ out)
{
    extern __shared__ float sm[];
    const int tid  = threadIdx.x;
    const int wid  = tid >> 5;
    const int lane = tid & 31;
    const long long e0 = (long long)blockIdx.x * TB;
    const float* __restrict__ dbase = data + e0 * 512;

    // -------- phase A: padded signal, transposed (coalesced global reads) --------
    float* sigt = sm + SIGT;  // 640 x 32, stride 33
    for (int idx = tid; idx < 64 * TB; idx += NTHREADS) {
        int p = idx >> 5, e = idx & 31;
        sigt[p * 33 + e] = 0.0f;
    }
    for (int idx = tid; idx < 512 * TB; idx += NTHREADS) {
        int e = idx >> 9, j = idx & 511;
        sigt[(64 + j) * 33 + e] = dbase[idx];
    }
    for (int idx = tid; idx < 64 * TB; idx += NTHREADS) {
        int e = idx >> 6, j = idx & 63;
        sigt[(576 + j) * 33 + e] = dbase[e * 512 + 510 - j];
    }
    __syncthreads();

    // -------- phase B: frame-quad layout sig2[k][e][t] --------
    for (int i = tid; i < 256 * 32; i += NTHREADS) {
        int k = i >> 5, e = i & 31;
        float4 v;
        v.x = sigt[k * 33 + e];
        v.y = sigt[(128 + k) * 33 + e];
        v.z = sigt[(256 + k) * 33 + e];
        v.w = sigt[(384 + k) * 33 + e];
        ((float4*)(sm + SIG2))[k * 32 + e] = v;
    }
    __syncthreads();

    // -------- phase C: STFT + magnitude (f32x2: (re,im) pairs, 8 filters/warp) --------
    {
        f32x2 acc[8][4];
        #pragma unroll
        for (int f = 0; f < 8; ++f)
            #pragma unroll
            for (int t = 0; t < 4; ++t) acc[f][t] = 0ull;

        const ulonglong2* __restrict__ wps = (const ulonglong2*)g_stft_wp;  // 66 per row
        const float4* __restrict__ s2 = (const float4*)(sm + SIG2);

        #pragma unroll 2
        for (int k = 0; k < 256; ++k) {
            float4 s4 = s2[k * 32 + lane];
            f32x2 S0 = b2(s4.x), S1 = b2(s4.y), S2 = b2(s4.z), S3 = b2(s4.w);
            ulonglong2 w0 = wps[k * 66 + wid * 4 + 0];
            ulonglong2 w1 = wps[k * 66 + wid * 4 + 1];
            ulonglong2 w2 = wps[k * 66 + wid * 4 + 2];
            ulonglong2 w3 = wps[k * 66 + wid * 4 + 3];
            f32x2 W[8] = {w0.x, w0.y, w1.x, w1.y, w2.x, w2.y, w3.x, w3.y};
            #pragma unroll
            for (int f = 0; f < 8; ++f) {
                acc[f][0] = ffma2(W[f], S0, acc[f][0]);
                acc[f][1] = ffma2(W[f], S1, acc[f][1]);
                acc[f][2] = ffma2(W[f], S2, acc[f][2]);
                acc[f][3] = ffma2(W[f], S3, acc[f][3]);
            }
        }
        #pragma unroll
        for (int f = 0; f < 8; ++f) {
            float4 mg;
            #pragma unroll
            for (int t = 0; t < 4; ++t) {
                float re, im; up2(acc[f][t], re, im);
                (&mg.x)[t] = sqrtf(re * re + im * im);
            }
            ((float4*)(sm + MAG))[(8 * wid + f) * 32 + lane] = mg;
        }

        // filter 128: each warp takes a k-slice of 16, partials to smem
        f32x2 r0 = 0ull, r1 = 0ull, r2 = 0ull, r3 = 0ull;
        int kb = wid * 16;
        #pragma unroll
        for (int k = kb; k < kb + 16; ++k) {
            float4 s4 = s2[k * 32 + lane];
            f32x2 W = *(const f32x2*)(g_stft_wp + k * 264 + 256);
            r0 = ffma2(W, b2(s4.x), r0);
            r1 = ffma2(W, b2(s4.y), r1);
            r2 = ffma2(W, b2(s4.z), r2);
            r3 = ffma2(W, b2(s4.w), r3);
        }
        float* fp = sm + FPART + (wid * 32 + lane) * 8;
        float lo, hi;
        up2(r0, lo, hi); fp[0] = lo; fp[1] = hi;
        up2(r1, lo, hi); fp[2] = lo; fp[3] = hi;
        up2(r2, lo, hi); fp[4] = lo; fp[5] = hi;
        up2(r3, lo, hi); fp[6] = lo; fp[7] = hi;
    }
    __syncthreads();
    if (tid < 128) {
        int e = tid & 31, t = tid >> 5;
        float re = 0.f, im = 0.f;
        #pragma unroll
        for (int w = 0; w < 16; ++w) {
            re += sm[FPART + (w * 32 + e) * 8 + 2 * t];
            im += sm[FPART + (w * 32 + e) * 8 + 2 * t + 1];
        }
        sm[MAG + (128 * 32 + e) * 4 + t] = sqrtf(re * re + im * im);
    }
    __syncthreads();

    // -------- e1: conv(129->128, k3, s1, p1), channel-pair packed --------
    {
        const float4* __restrict__ mg = (const float4*)(sm + MAG);
        #pragma unroll
        for (int p = 0; p < 2; ++p) {
            int g = wid * 2 + p;                       // channel quad 4g..4g+3
            ulonglong2 bb = *(const ulonglong2*)(e1_b + 4 * g);
            f32x2 a[2][4];
            #pragma unroll
            for (int t = 0; t < 4; ++t) { a[0][t] = bb.x; a[1][t] = bb.y; }
            const ulonglong2* __restrict__ wq = (const ulonglong2*)g_e1_wp + (long)g * 129 * 3;
            #pragma unroll 2
            for (int c = 0; c < 129; ++c) {
                float4 m4 = mg[c * 32 + lane];
                f32x2 M0 = b2(m4.x), M1 = b2(m4.y), M2 = b2(m4.z), M3 = b2(m4.w);
                ulonglong2 W0 = wq[c * 3 + 0];
                ulonglong2 W1 = wq[c * 3 + 1];
                ulonglong2 W2 = wq[c * 3 + 2];
                a[0][0] = ffma2(W1.x, M0, ffma2(W2.x, M1, a[0][0]));
                a[0][1] = ffma2(W0.x, M0, ffma2(W1.x, M1, ffma2(W2.x, M2, a[0][1])));
                a[0][2] = ffma2(W0.x, M1, ffma2(W1.x, M2, ffma2(W2.x, M3, a[0][2])));
                a[0][3] = ffma2(W0.x, M2, ffma2(W1.x, M3, a[0][3]));
                a[1][0] = ffma2(W1.y, M0, ffma2(W2.y, M1, a[1][0]));
                a[1][1] = ffma2(W0.y, M0, ffma2(W1.y, M1, ffma2(W2.y, M2, a[1][1])));
                a[1][2] = ffma2(W0.y, M1, ffma2(W1.y, M2, ffma2(W2.y, M3, a[1][2])));
                a[1][3] = ffma2(W0.y, M2, ffma2(W1.y, M3, a[1][3]));
            }
            #pragma unroll
            for (int P = 0; P < 2; ++P) {
                int chA = 4 * g + 2 * P;
                float4 va, vb;
                #pragma unroll
                for (int t = 0; t < 4; ++t) {
                    float lo, hi; up2(a[P][t], lo, hi);
                    (&va.x)[t] = fmaxf(lo, 0.f);
                    (&vb.x)[t] = fmaxf(hi, 0.f);
                }
                ((float4*)(sm + Y1))[chA * 32 + lane]       = va;
                ((float4*)(sm + Y1))[(chA + 1) * 32 + lane] = vb;
            }
        }
    }
    __syncthreads();

    // -------- e2: conv(128->64, k3, s2, p1), len 4 -> 2 --------
    {
        int g = wid;                                   // channels 4g..4g+3
        ulonglong2 bb = *(const ulonglong2*)(e2_b + 4 * g);
        f32x2 a[2][2];
        a[0][0] = bb.x; a[0][1] = bb.x;
        a[1][0] = bb.y; a[1][1] = bb.y;
        const ulonglong2* __restrict__ wq = (const ulonglong2*)g_e2_wp + (long)g * 128 * 3;
        const float4* __restrict__ y1p = (const float4*)(sm + Y1);
        #pragma unroll 2
        for (int c = 0; c < 128; ++c) {
            float4 v4 = y1p[c * 32 + lane];
            f32x2 V0 = b2(v4.x), V1 = b2(v4.y), V2 = b2(v4.z), V3 = b2(v4.w);
            ulonglong2 W0 = wq[c * 3 + 0];
            ulonglong2 W1 = wq[c * 3 + 1];
            ulonglong2 W2 = wq[c * 3 + 2];
            a[0][0] = ffma2(W1.x, V0, ffma2(W2.x, V1, a[0][0]));
            a[0][1] = ffma2(W0.x, V1, ffma2(W1.x, V2, ffma2(W2.x, V3, a[0][1])));
            a[1][0] = ffma2(W1.y, V0, ffma2(W2.y, V1, a[1][0]));
            a[1][1] = ffma2(W0.y, V1, ffma2(W1.y, V2, ffma2(W2.y, V3, a[1][1])));
        }
        #pragma unroll
        for (int P = 0; P < 2; ++P) {
            int chA = 4 * g + 2 * P;
            float l0, h0, l1, h1;
            up2(a[P][0], l0, h0); up2(a[P][1], l1, h1);
            ((float2*)(sm + Y2))[chA * 32 + lane]       = make_float2(fmaxf(l0, 0.f), fmaxf(l1, 0.f));
            ((float2*)(sm + Y2))[(chA + 1) * 32 + lane] = make_float2(fmaxf(h0, 0.f), fmaxf(h1, 0.f));
        }
    }
    __syncthreads();

    // -------- e3: conv(64->64, k3, s2, p1), len 2 -> 1 (tap-pair packed) --------
    {
        int g = wid;                                   // channels 4g..4g+3
        f32x2 acc[4] = {0ull, 0ull, 0ull, 0ull};
        const ulonglong2* __restrict__ wq = (const ulonglong2*)g_e3_wp + (long)g * 64 * 2;
        #pragma unroll 2
        for (int c = 0; c < 64; ++c) {
            f32x2 v01 = *(const f32x2*)(sm + Y2 + (c * 32 + lane) * 2);
            ulonglong2 L0 = wq[c * 2], L1 = wq[c * 2 + 1];
            acc[0] = ffma2(L0.x, v01, acc[0]);
            acc[1] = ffma2(L0.y, v01, acc[1]);
            acc[2] = ffma2(L1.x, v01, acc[2]);
            acc[3] = ffma2(L1.y, v01, acc[3]);
        }
        #pragma unroll
        for (int m = 0; m < 4; ++m) {
            float lo, hi; up2(acc[m], lo, hi);
            sm[Y3 + (4 * g + m) * 32 + lane] = fmaxf(lo + hi + e3_b[4 * g + m], 0.f);
        }
    }
    __syncthreads();

    // -------- e4: conv(64->128, k3, s1, p1), len 1 (center tap only) --------
    {
        int q0 = wid * 2, q1 = wid * 2 + 1;            // channel quads; 8 channels/warp
        ulonglong2 bA = *(const ulonglong2*)(e4_b + 8 * wid);
        ulonglong2 bB = *(const ulonglong2*)(e4_b + 8 * wid + 4);
        f32x2 aA0 = bA.x, aA1 = bA.y, aB0 = bB.x, aB1 = bB.y;
        const ulonglong2* __restrict__ wq = (const ulonglong2*)g_e4_wp;
        #pragma unroll 2
        for (int c = 0; c < 64; ++c) {
            f32x2 V = b2(sm[Y3 + c * 32 + lane]);
            ulonglong2 WA = wq[q0 * 64 + c];
            ulonglong2 WB = wq[q1 * 64 + c];
            aA0 = ffma2(WA.x, V, aA0); aA1 = ffma2(WA.y, V, aA1);
            aB0 = ffma2(WB.x, V, aB0); aB1 = ffma2(WB.y, V, aB1);
        }
        float l0, h0, l1, h1;
        up2(aA0, l0, h0); up2(aA1, l1, h1);
        ((float4*)(sm + Y4))[q0 * 32 + lane] =
            make_float4(fmaxf(l0, 0.f), fmaxf(h0, 0.f), fmaxf(l1, 0.f), fmaxf(h1, 0.f));
        up2(aB0, l0, h0); up2(aB1, l1, h1);
        ((float4*)(sm + Y4))[q1 * 32 + lane] =
            make_float4(fmaxf(l0, 0.f), fmaxf(h0, 0.f), fmaxf(l1, 0.f), fmaxf(h1, 0.f));
    }
    __syncthreads();

    // -------- LSTM cell (h0=c0=0 => gates i,g,o) + decoder dot --------
    {
        float psum = 0.f;
        const ulonglong2* __restrict__ W = (const ulonglong2*)w_ih;  // 32 ull2 per row
        const ulonglong2* __restrict__ y4p = (const ulonglong2*)(sm + Y4);
        #pragma unroll
        for (int ib = 0; ib < 2; ++ib) {
            int ch0 = wid * 8 + ib * 4;
            f32x2 ai[4] = {0ull,0ull,0ull,0ull};
            f32x2 ag[4] = {0ull,0ull,0ull,0ull};
            f32x2 ao[4] = {0ull,0ull,0ull,0ull};
            #pragma unroll 2
            for (int c4 = 0; c4 < 32; ++c4) {
                ulonglong2 V = y4p[c4 * 32 + lane];
                #pragma unroll
                for (int i = 0; i < 4; ++i) {
                    int ch = ch0 + i;
                    ulonglong2 wi = W[(ch)       * 32 + c4];
                    ulonglong2 wg = W[(ch + 256) * 32 + c4];
                    ulonglong2 wo = W[(ch + 384) * 32 + c4];
                    ai[i] = ffma2(wi.x, V.x, ai[i]); ai[i] = ffma2(wi.y, V.y, ai[i]);
                    ag[i] = ffma2(wg.x, V.x, ag[i]); ag[i] = ffma2(wg.y, V.y, ag[i]);
                    ao[i] = ffma2(wo.x, V.x, ao[i]); ao[i] = ffma2(wo.y, V.y, ao[i]);
                }
            }
            #pragma unroll
            for (int i = 0; i < 4; ++i) {
                int ch = ch0 + i;
                float lo, hi;
                up2(ai[i], lo, hi); float gi = lo + hi + b_ih[ch]       + b_hh[ch];
                up2(ag[i], lo, hi); float gg = lo + hi + b_ih[ch + 256] + b_hh[ch + 256];
                up2(ao[i], lo, hi); float go = lo + hi + b_ih[ch + 384] + b_hh[ch + 384];
                float cc = sigmoidf_(gi) * tanhf(gg);
                float h  = sigmoidf_(go) * tanhf(cc);
                psum = fmaf(fmaxf(h, 0.f), dec_w[ch], psum);
            }
        }
        sm[PARTS + wid * 32 + lane] = psum;
    }
    __syncthreads();

    if (wid == 0) {
        float acc = dec_b[0];
        #pragma unroll
        for (int w = 0; w < 16; ++w) acc += sm[PARTS + w * 32 + lane];
        out[e0 + lane] = sigmoidf_(acc);
    }
}

extern "C" void kernel_launch(void* const* d_in, const int* in_sizes, int n_in,
                              void* d_out, int out_size)
{
    const float* data   = (const float*)d_in[0];
    // d_in[1] = sr (16000 -> context 64; unused)
    const float* stft_w = (const float*)d_in[2];
    const float* e1_w   = (const float*)d_in[3];
    const float* e1_b   = (const float*)d_in[4];
    const float* e2_w   = (const float*)d_in[5];
    const float* e2_b   = (const float*)d_in[6];
    const float* e3_w   = (const float*)d_in[7];
    const float* e3_b   = (const float*)d_in[8];
    const float* e4_w   = (const float*)d_in[9];
    const float* e4_b   = (const float*)d_in[10];
    const float* w_ih   = (const float*)d_in[11];
    // d_in[12] = w_hh (unused: h0 = 0)
    const float* b_ih   = (const float*)d_in[13];
    const float* b_hh   = (const float*)d_in[14];
    const float* dec_w  = (const float*)d_in[15];
    const float* dec_b  = (const float*)d_in[16];
    float* out = (float*)d_out;

    vad_prep<<<64, 256>>>(stft_w, e1_w, e2_w, e3_w, e4_w);

    int B = in_sizes[0] / 512;
    int grid = B / TB;
    size_t smem = SMEM_FLOATS * sizeof(float);
    cudaFuncSetAttribute(vad_fused, cudaFuncAttributeMaxDynamicSharedMemorySize, (int)smem);
    vad_fused<<<grid, NTHREADS, smem>>>(data,
                                        e1_b, e2_b, e3_b, e4_b,
                                        w_ih, b_ih, b_hh, dec_w, dec_b, out);
}